// round 13
// baseline (speedup 1.0000x reference)
#include <cuda_runtime.h>
#include <cuda_fp16.h>
#include <cstdint>
#include <math.h>

// Problem dims
#define BB 2
#define SS 2048
#define DD 1024
#define HH 16
#define DH 64
#define FF 4096
#define EE 8
#define NT (BB*SS)   // 4096 tokens

// ---------------- scratch ----------------
__device__ __half g_h16[NT*DD];
__device__ __half g_q16[NT*DD];
__device__ __half g_k16[NT*DD];
__device__ __half g_vT16[(size_t)BB*HH*DH*SS];  // V transposed: [bh][d][s]
__device__ __half g_attn16[NT*DD];
__device__ float  g_x1[NT*DD];
__device__ __half g_x116[NT*DD];
__device__ int    g_cnt[EE];
__device__ int    g_tok[EE*NT];
__device__ int    g_slotid[EE*NT];
__device__ float  g_wt[EE*NT];
__device__ __half g_h116[(size_t)EE*NT*FF];
__device__ float  g_contrib[(size_t)2*NT*DD];
__device__ __half g_WqT16[DD*DD];
__device__ __half g_WkT16[DD*DD];
__device__ __half g_WvT16[DD*DD];
__device__ __half g_WoT16[DD*DD];
__device__ __half g_W1T16[(size_t)EE*(size_t)FF*DD];
__device__ __half g_W2T16[(size_t)EE*(size_t)DD*FF];

// ---------------- cp.async helpers ----------------
__device__ __forceinline__ void cpa16(const void* dst, const void* src) {
    unsigned d = (unsigned)__cvta_generic_to_shared(dst);
    asm volatile("cp.async.cg.shared.global [%0], [%1], 16;" :: "r"(d), "l"(src));
}
#define CPA_COMMIT()  asm volatile("cp.async.commit_group;")
#define CPA_WAIT(N)   asm volatile("cp.async.wait_group %0;" :: "n"(N))

// fp16 m16n8k16, fp32 accum
__device__ __forceinline__ void mma16(float (&c)[4], const uint32_t (&a)[4],
                                      uint32_t b0, uint32_t b1) {
    asm volatile("mma.sync.aligned.m16n8k16.row.col.f32.f16.f16.f32 "
        "{%0,%1,%2,%3}, {%4,%5,%6,%7}, {%8,%9}, {%0,%1,%2,%3};"
        : "+f"(c[0]), "+f"(c[1]), "+f"(c[2]), "+f"(c[3])
        : "r"(a[0]), "r"(a[1]), "r"(a[2]), "r"(a[3]), "r"(b0), "r"(b1));
}
// ldmatrix x4 (b16)
__device__ __forceinline__ void ldsm4(uint32_t (&r)[4], uint32_t addr) {
    asm volatile("ldmatrix.sync.aligned.m8n8.x4.shared.b16 {%0,%1,%2,%3}, [%4];"
        : "=r"(r[0]), "=r"(r[1]), "=r"(r[2]), "=r"(r[3]) : "r"(addr));
}

// ---------------- fp16 GEMM core (ldmatrix fragments, single barrier per K-slab) ----------------
#define HSTR 40
#define STG_HALVES (128*HSTR)
#define GEMM16_SMEM (8*STG_HALVES*2)

__device__ __forceinline__ void gemm16_core(const __half* a_src, const __half* b_src,
                                            int Kd, float (&acc)[4][4][4], __half* smem) {
    const int t = threadIdx.x;
    const int lane = t & 31, warp = t >> 5;
    const int wm = (warp >> 2) * 64, wn = (warp & 3) * 32;
    const int r = t >> 1, h = t & 1;

    __half* Asm = smem;
    __half* Bsm = smem + 4 * STG_HALVES;
    __half* ad0 = Asm + (size_t)r * HSTR + h * 16;
    __half* bd0 = Bsm + (size_t)r * HSTR + h * 16;

    const int a_row = (lane & 7) + ((lane >> 3) & 1) * 8;
    const int a_col = (lane >> 4) * 8;
    const int b_row = (lane & 7) + (lane >> 4) * 8;
    const int b_col = ((lane >> 3) & 1) * 8;
    uint32_t As_u = (uint32_t)__cvta_generic_to_shared(Asm);
    uint32_t Bs_u = (uint32_t)__cvta_generic_to_shared(Bsm);
    uint32_t aoff[4];
#pragma unroll
    for (int i = 0; i < 4; i++)
        aoff[i] = ((wm + i*16 + a_row) * HSTR + a_col) * 2;
    uint32_t boff0 = ((wn +      b_row) * HSTR + b_col) * 2;
    uint32_t boff1 = ((wn + 16 + b_row) * HSTR + b_col) * 2;

#define LD_STAGE(s, buf) { \
        const __half* as_ = a_src + (s) * 32; \
        const __half* bs_ = b_src + (s) * 32; \
        __half* ad_ = ad0 + (buf) * STG_HALVES; \
        __half* bd_ = bd0 + (buf) * STG_HALVES; \
        cpa16(ad_, as_); cpa16(ad_ + 8, as_ + 8); \
        cpa16(bd_, bs_); cpa16(bd_ + 8, bs_ + 8); }

    const int steps = Kd / 32;
    LD_STAGE(0, 0); CPA_COMMIT();
    LD_STAGE(1, 1); CPA_COMMIT();
    LD_STAGE(2, 2); CPA_COMMIT();

    for (int s = 0; s < steps; s++) {
        CPA_WAIT(2);
        __syncthreads();
        const int nx = s + 3;
        if (nx < steps) LD_STAGE(nx, nx & 3);
        CPA_COMMIT();
        const uint32_t Asb = As_u + (s & 3) * STG_HALVES * 2;
        const uint32_t Bsb = Bs_u + (s & 3) * STG_HALVES * 2;
#pragma unroll
        for (int ks = 0; ks < 2; ks++) {
            const uint32_t kadd = ks * 32;
            uint32_t a[4][4], b0[4], b1[4];
#pragma unroll
            for (int i = 0; i < 4; i++) ldsm4(a[i], Asb + aoff[i] + kadd);
            ldsm4(b0, Bsb + boff0 + kadd);
            ldsm4(b1, Bsb + boff1 + kadd);
#pragma unroll
            for (int i = 0; i < 4; i++) {
                mma16(acc[i][0], a[i], b0[0], b0[1]);
                mma16(acc[i][1], a[i], b0[2], b0[3]);
                mma16(acc[i][2], a[i], b1[0], b1[1]);
                mma16(acc[i][3], a[i], b1[2], b1[3]);
            }
        }
    }
#undef LD_STAGE
}

// ---------------- transpose + fp32->fp16 ----------------
__global__ void tr16_kernel(const float* __restrict__ src, __half* __restrict__ dst,
                            int R, int C) {
    __shared__ float tl[32][33];
    const size_t zsrc = (size_t)blockIdx.z * R * C;
    const int bx = blockIdx.x * 32, by = blockIdx.y * 32;
    const int tx = threadIdx.x, ty = threadIdx.y;
#pragma unroll
    for (int i = 0; i < 32; i += 8)
        tl[ty + i][tx] = src[zsrc + (size_t)(by + ty + i) * C + bx + tx];
    __syncthreads();
#pragma unroll
    for (int i = 0; i < 32; i += 8)
        dst[zsrc + (size_t)(bx + ty + i) * R + by + tx] = __float2half(tl[tx][ty + i]);
}

// ---------------- layernorm (fp16 out) ----------------
__global__ void ln_kernel(const float* __restrict__ x, const float* __restrict__ g,
                          const float* __restrict__ b) {
    __shared__ float red[256];
    int t = blockIdx.x, tid = threadIdx.x;
    const float* xr = x + (size_t)t * DD;
    float v[4], s = 0.f, s2 = 0.f;
#pragma unroll
    for (int i = 0; i < 4; i++) {
        float vv = xr[tid + i*256];
        v[i] = vv; s += vv; s2 += vv*vv;
    }
    red[tid] = s; __syncthreads();
    for (int o = 128; o > 0; o >>= 1) { if (tid < o) red[tid] += red[tid+o]; __syncthreads(); }
    float mean = red[0] * (1.f/DD);
    __syncthreads();
    red[tid] = s2; __syncthreads();
    for (int o = 128; o > 0; o >>= 1) { if (tid < o) red[tid] += red[tid+o]; __syncthreads(); }
    float var = red[0] * (1.f/DD) - mean*mean;
    float rs = rsqrtf(var + 1e-5f);
    __half* out = g_h16 + (size_t)t * DD;
#pragma unroll
    for (int i = 0; i < 4; i++) {
        int c = tid + i*256;
        out[c] = __float2half((v[i]-mean)*rs*g[c] + b[c]);
    }
}

// ---------------- QKV (fp16 mma; Q/K fp16 token-major, V transposed) ----------------
__global__ void tc16_qkv(const __half* __restrict__ BqT, const __half* __restrict__ BkT,
                         const __half* __restrict__ BvT) {
    extern __shared__ __half smh[];
    const __half* BT = blockIdx.z == 0 ? BqT : blockIdx.z == 1 ? BkT : BvT;
    const int m0 = blockIdx.y * 128, n0 = blockIdx.x * 128;
    const int t = threadIdx.x, lane = t & 31, warp = t >> 5;
    const int g = lane >> 2, q = lane & 3;
    const int wm = (warp >> 2) * 64, wn = (warp & 3) * 32;
    const int r = t >> 1, h = t & 1;
    float acc[4][4][4] = {};
    const __half* a_src = g_h16 + (size_t)(m0 + r) * DD + h * 16;
    const __half* b_src = BT + (size_t)(n0 + r) * DD + h * 16;
    gemm16_core(a_src, b_src, DD, acc, smh);

    if (blockIdx.z == 2) {
#pragma unroll
        for (int i = 0; i < 4; i++) {
            int r0 = m0 + wm + i*16 + g;
#pragma unroll
            for (int j = 0; j < 4; j++) {
                int c0 = n0 + wn + j*8 + 2*q;
                int hh = c0 >> 6, dd = c0 & 63;
#pragma unroll
                for (int hf = 0; hf < 2; hf++) {
                    int row = r0 + hf*8;
                    int b_ = row >> 11, s_ = row & 2047;
                    size_t basev = ((size_t)(b_*HH + hh) * DH);
                    g_vT16[(basev + dd)     * SS + s_] = __float2half(acc[i][j][hf*2+0]);
                    g_vT16[(basev + dd + 1) * SS + s_] = __float2half(acc[i][j][hf*2+1]);
                }
            }
        }
    } else {
        __half* C = blockIdx.z == 0 ? g_q16 : g_k16;
#pragma unroll
        for (int i = 0; i < 4; i++) {
            int r0 = m0 + wm + i*16 + g;
#pragma unroll
            for (int j = 0; j < 4; j++) {
                int c0 = n0 + wn + j*8 + 2*q;
                *(__half2*)&C[(size_t)r0 * DD + c0] =
                    __floats2half2_rn(acc[i][j][0], acc[i][j][1]);
                *(__half2*)&C[(size_t)(r0+8) * DD + c0] =
                    __floats2half2_rn(acc[i][j][2], acc[i][j][3]);
            }
        }
    }
}

// ---------------- fp16 flash attention (ldmatrix fragments) ----------------
#define AST 72
#define ATT_SMEM ((128*AST + 2*64*AST + 2*64*AST) * 2)
__global__ void attn16() {
    extern __shared__ __half ash[];
    __half (*Qs)[AST]       = (__half(*)[AST])ash;                       // [128][72], reused as P
    __half (*Ks)[64][AST]   = (__half(*)[64][AST])(ash + 128*AST);
    __half (*Vts)[64][AST]  = (__half(*)[64][AST])(ash + 128*AST + 2*64*AST);

    const int tid = threadIdx.x;
    const int lane = tid & 31, w = tid >> 5;
    const int g = lane >> 2, q = lane & 3;
    const int bh = blockIdx.y, b = bh >> 4, h = bh & 15;
    const int q0 = blockIdx.x * 128;
    const size_t tokbase = ((size_t)b*SS)*DD + h*DH;
    const size_t vtbase  = (size_t)bh * DH * SS;
    const int pr = w * 16;

    // ldmatrix per-thread addressing
    const int a_row = (lane & 7) + ((lane >> 3) & 1) * 8;
    const int a_col = (lane >> 4) * 8;
    const int b_row = (lane & 7) + (lane >> 4) * 8;
    const int b_col = ((lane >> 3) & 1) * 8;
    const uint32_t Qs_u  = (uint32_t)__cvta_generic_to_shared(Qs);
    const uint32_t Ks_u  = (uint32_t)__cvta_generic_to_shared(Ks);
    const uint32_t Vts_u = (uint32_t)__cvta_generic_to_shared(Vts);
    const uint32_t a_off = ((pr + a_row) * AST + a_col) * 2;   // within Qs/Ps
    const uint32_t KBUF = 64 * AST * 2;                        // bytes per K/V buffer

    { // Q tile (group A, with KV tile 0)
        int r = tid >> 1, cq = (tid & 1) * 32;
        const __half* src = g_q16 + tokbase + (size_t)(q0 + r)*DD + cq;
        cpa16(&Qs[r][cq],      src);      cpa16(&Qs[r][cq + 8],  src + 8);
        cpa16(&Qs[r][cq + 16], src + 16); cpa16(&Qs[r][cq + 24], src + 24);
    }
    {
        int r = tid >> 2, cq = (tid & 3) * 16;
        const __half* ksrc = g_k16 + tokbase + (size_t)r*DD + cq;
        cpa16(&Ks[0][r][cq], ksrc); cpa16(&Ks[0][r][cq + 8], ksrc + 8);
        const __half* vsrc = g_vT16 + vtbase + (size_t)r*SS + cq;
        cpa16(&Vts[0][r][cq], vsrc); cpa16(&Vts[0][r][cq + 8], vsrc + 8);
    }
    CPA_COMMIT();
    {
        int r = tid >> 2, cq = (tid & 3) * 16;
        const __half* ksrc = g_k16 + tokbase + (size_t)(64 + r)*DD + cq;
        cpa16(&Ks[1][r][cq], ksrc); cpa16(&Ks[1][r][cq + 8], ksrc + 8);
        const __half* vsrc = g_vT16 + vtbase + (size_t)r*SS + 64 + cq;
        cpa16(&Vts[1][r][cq], vsrc); cpa16(&Vts[1][r][cq + 8], vsrc + 8);
    }
    CPA_COMMIT();

    CPA_WAIT(1);
    __syncthreads();

    uint32_t aq[4][4];
#pragma unroll
    for (int ks = 0; ks < 4; ks++) ldsm4(aq[ks], Qs_u + a_off + ks*32);

    float m0r = -1e30f, m1r = -1e30f, l0 = 0.f, l1 = 0.f;
    float acc_o[8][4];
#pragma unroll
    for (int j = 0; j < 8; j++) { acc_o[j][0]=0.f; acc_o[j][1]=0.f; acc_o[j][2]=0.f; acc_o[j][3]=0.f; }
    __half (*Ps)[AST] = Qs;

    for (int kt = 0; kt < SS/64; kt++) {
        CPA_WAIT(1);
        __syncthreads();
        const uint32_t kb_u = Ks_u  + (kt & 1) * KBUF;
        const uint32_t vb_u = Vts_u + (kt & 1) * KBUF;

        // scores (fp16 k16) — B fragments via ldmatrix
        float s[8][4];
#pragma unroll
        for (int j = 0; j < 8; j++) { s[j][0]=0.f; s[j][1]=0.f; s[j][2]=0.f; s[j][3]=0.f; }
#pragma unroll
        for (int ks = 0; ks < 4; ks++) {
            const uint32_t kadd = ks * 32;
#pragma unroll
            for (int p = 0; p < 4; p++) {
                uint32_t bk[4];
                ldsm4(bk, kb_u + ((p*16 + b_row) * AST + b_col) * 2 + kadd);
                mma16(s[2*p],   aq[ks], bk[0], bk[1]);
                mma16(s[2*p+1], aq[ks], bk[2], bk[3]);
            }
        }
        // online softmax (scale 0.125)
        float mx0 = m0r, mx1 = m1r;
#pragma unroll
        for (int j = 0; j < 8; j++) {
            s[j][0] *= 0.125f; s[j][1] *= 0.125f; s[j][2] *= 0.125f; s[j][3] *= 0.125f;
            mx0 = fmaxf(mx0, fmaxf(s[j][0], s[j][1]));
            mx1 = fmaxf(mx1, fmaxf(s[j][2], s[j][3]));
        }
        mx0 = fmaxf(mx0, __shfl_xor_sync(0xffffffffu, mx0, 1));
        mx0 = fmaxf(mx0, __shfl_xor_sync(0xffffffffu, mx0, 2));
        mx1 = fmaxf(mx1, __shfl_xor_sync(0xffffffffu, mx1, 1));
        mx1 = fmaxf(mx1, __shfl_xor_sync(0xffffffffu, mx1, 2));
        float alpha0 = __expf(m0r - mx0), alpha1 = __expf(m1r - mx1);
        m0r = mx0; m1r = mx1;
        float ps0 = 0.f, ps1 = 0.f;
#pragma unroll
        for (int j = 0; j < 8; j++) {
            s[j][0] = __expf(s[j][0] - mx0); ps0 += s[j][0];
            s[j][1] = __expf(s[j][1] - mx0); ps0 += s[j][1];
            s[j][2] = __expf(s[j][2] - mx1); ps1 += s[j][2];
            s[j][3] = __expf(s[j][3] - mx1); ps1 += s[j][3];
        }
        ps0 += __shfl_xor_sync(0xffffffffu, ps0, 1);
        ps0 += __shfl_xor_sync(0xffffffffu, ps0, 2);
        ps1 += __shfl_xor_sync(0xffffffffu, ps1, 1);
        ps1 += __shfl_xor_sync(0xffffffffu, ps1, 2);
        l0 = l0 * alpha0 + ps0;
        l1 = l1 * alpha1 + ps1;
#pragma unroll
        for (int j = 0; j < 8; j++) {
            acc_o[j][0] *= alpha0; acc_o[j][1] *= alpha0;
            acc_o[j][2] *= alpha1; acc_o[j][3] *= alpha1;
        }
        // stash P (fp16) into warp-local rows
#pragma unroll
        for (int j = 0; j < 8; j++) {
            *(__half2*)&Ps[pr+g][j*8 + 2*q]   = __floats2half2_rn(s[j][0], s[j][1]);
            *(__half2*)&Ps[pr+8+g][j*8 + 2*q] = __floats2half2_rn(s[j][2], s[j][3]);
        }
        __syncwarp();
        // PV (fp16 k16) — A and B fragments via ldmatrix
#pragma unroll
        for (int ks = 0; ks < 4; ks++) {
            const uint32_t kadd = ks * 32;
            uint32_t ap[4];
            ldsm4(ap, Qs_u + a_off + kadd);   // Ps overlays Qs
#pragma unroll
            for (int p = 0; p < 4; p++) {
                uint32_t bv[4];
                ldsm4(bv, vb_u + ((p*16 + b_row) * AST + b_col) * 2 + kadd);
                mma16(acc_o[2*p],   ap, bv[0], bv[1]);
                mma16(acc_o[2*p+1], ap, bv[2], bv[3]);
            }
        }
        __syncthreads();
        if (kt + 2 < SS/64) {
            int r = tid >> 2, cq = (tid & 3) * 16;
            const int buf = kt & 1;
            const __half* ksrc = g_k16 + tokbase + (size_t)((kt+2)*64 + r)*DD + cq;
            cpa16(&Ks[buf][r][cq], ksrc); cpa16(&Ks[buf][r][cq + 8], ksrc + 8);
            const __half* vsrc = g_vT16 + vtbase + (size_t)r*SS + (kt+2)*64 + cq;
            cpa16(&Vts[buf][r][cq], vsrc); cpa16(&Vts[buf][r][cq + 8], vsrc + 8);
        }
        CPA_COMMIT();
    }
    // epilogue
    float inv0 = 1.f / l0, inv1 = 1.f / l1;
    int row0 = q0 + pr + g;
#pragma unroll
    for (int j = 0; j < 8; j++) {
        int col = j*8 + 2*q;
        *(__half2*)&g_attn16[tokbase + (size_t)row0 * DD + col] =
            __floats2half2_rn(acc_o[j][0]*inv0, acc_o[j][1]*inv0);
        *(__half2*)&g_attn16[tokbase + (size_t)(row0+8) * DD + col] =
            __floats2half2_rn(acc_o[j][2]*inv1, acc_o[j][3]*inv1);
    }
}

// ---------------- O-proj + residual ----------------
__global__ void tc16_oproj(const __half* __restrict__ BT, const float* __restrict__ Rres) {
    extern __shared__ __half smh[];
    const int m0 = blockIdx.y * 128, n0 = blockIdx.x * 128;
    const int t = threadIdx.x, lane = t & 31, warp = t >> 5;
    const int g = lane >> 2, q = lane & 3;
    const int wm = (warp >> 2) * 64, wn = (warp & 3) * 32;
    const int r = t >> 1, h = t & 1;
    float acc[4][4][4] = {};
    const __half* a_src = g_attn16 + (size_t)(m0 + r) * DD + h * 16;
    const __half* b_src = BT + (size_t)(n0 + r) * DD + h * 16;
    gemm16_core(a_src, b_src, DD, acc, smh);
#pragma unroll
    for (int i = 0; i < 4; i++) {
        int r0 = m0 + wm + i*16 + g;
#pragma unroll
        for (int j = 0; j < 4; j++) {
            int c0 = n0 + wn + j*8 + 2*q;
#pragma unroll
            for (int hf = 0; hf < 2; hf++) {
                size_t idx = (size_t)(r0 + hf*8) * DD + c0;
                float2 u = *(const float2*)&Rres[idx];
                float v0 = acc[i][j][hf*2+0] + u.x;
                float v1 = acc[i][j][hf*2+1] + u.y;
                *(float2*)&g_x1[idx] = make_float2(v0, v1);
                *(__half2*)&g_x116[idx] = __floats2half2_rn(v0, v1);
            }
        }
    }
}

// ---------------- FFN1 ----------------
__global__ void tc16_ffn1(const __half* __restrict__ W1T, const float* __restrict__ b1) {
    const int e = blockIdx.z;
    const int cnt = g_cnt[e];
    const int m0 = blockIdx.y * 128;
    if (m0 >= cnt) return;
    extern __shared__ __half smh[];
    const int n0 = blockIdx.x * 128;
    const int t = threadIdx.x, lane = t & 31, warp = t >> 5;
    const int g = lane >> 2, q = lane & 3;
    const int wm = (warp >> 2) * 64, wn = (warp & 3) * 32;
    const int r = t >> 1, h = t & 1;
    int ar = m0 + r; if (ar > cnt - 1) ar = cnt - 1;
    const int tok = g_tok[e * NT + ar];
    float acc[4][4][4] = {};
    const __half* a_src = g_x116 + (size_t)tok * DD + h * 16;
    const __half* b_src = W1T + (size_t)e * FF * DD + (size_t)(n0 + r) * DD + h * 16;
    gemm16_core(a_src, b_src, DD, acc, smh);
#pragma unroll
    for (int i = 0; i < 4; i++) {
        int r0 = m0 + wm + i*16 + g;
#pragma unroll
        for (int j = 0; j < 4; j++) {
            int c0 = n0 + wn + j*8 + 2*q;
            float bb0 = b1[e*FF + c0], bb1 = b1[e*FF + c0 + 1];
#pragma unroll
            for (int hf = 0; hf < 2; hf++) {
                int rr = r0 + hf*8;
                if (rr >= cnt) continue;
                float u0 = acc[i][j][hf*2+0] + bb0;
                float u1 = acc[i][j][hf*2+1] + bb1;
                float g0 = 0.5f*u0*(1.f + tanhf(0.7978845608028654f*(u0 + 0.044715f*u0*u0*u0)));
                float g1 = 0.5f*u1*(1.f + tanhf(0.7978845608028654f*(u1 + 0.044715f*u1*u1*u1)));
                *(__half2*)&g_h116[((size_t)e*NT + rr)*FF + c0] = __floats2half2_rn(g0, g1);
            }
        }
    }
}

// ---------------- FFN2 ----------------
__global__ void tc16_ffn2(const __half* __restrict__ W2T, const float* __restrict__ b2) {
    const int e = blockIdx.z;
    const int cnt = g_cnt[e];
    const int m0 = blockIdx.y * 128;
    if (m0 >= cnt) return;
    extern __shared__ __half smh[];
    const int n0 = blockIdx.x * 128;
    const int t = threadIdx.x, lane = t & 31, warp = t >> 5;
    const int g = lane >> 2, q = lane & 3;
    const int wm = (warp >> 2) * 64, wn = (warp & 3) * 32;
    const int r = t >> 1, h = t & 1;
    int ar = m0 + r; if (ar > cnt - 1) ar = cnt - 1;
    float acc[4][4][4] = {};
    const __half* a_src = g_h116 + ((size_t)e*NT + ar) * FF + h * 16;
    const __half* b_src = W2T + (size_t)e * DD * FF + (size_t)(n0 + r) * FF + h * 16;
    gemm16_core(a_src, b_src, FF, acc, smh);
#pragma unroll
    for (int i = 0; i < 4; i++) {
        int r0 = m0 + wm + i*16 + g;
#pragma unroll
        for (int j = 0; j < 4; j++) {
            int c0 = n0 + wn + j*8 + 2*q;
            float bb0 = b2[e*DD + c0], bb1 = b2[e*DD + c0 + 1];
#pragma unroll
            for (int hf = 0; hf < 2; hf++) {
                int rr = r0 + hf*8;
                if (rr >= cnt) continue;
                int slot = g_slotid[e*NT + rr];
                float w  = g_wt[e*NT + rr];
                *(float2*)&g_contrib[(size_t)slot * DD + c0] =
                    make_float2(w * (acc[i][j][hf*2+0] + bb0),
                                w * (acc[i][j][hf*2+1] + bb1));
            }
        }
    }
}

// ---------------- gate ----------------
__global__ void zero_cnt_kernel() { if (threadIdx.x < EE) g_cnt[threadIdx.x] = 0; }

__global__ void gate_kernel(const float* __restrict__ Wg) {
    __shared__ float lg[EE];
    int t = blockIdx.x, tid = threadIdx.x;
    int w = tid >> 5, lane = tid & 31;
    const float* xr = g_x1 + (size_t)t * DD;
    float s = 0.f;
    for (int d = lane; d < DD; d += 32) s += xr[d] * Wg[d*EE + w];
#pragma unroll
    for (int o = 16; o > 0; o >>= 1) s += __shfl_down_sync(0xffffffffu, s, o);
    if (lane == 0) lg[w] = s;
    __syncthreads();
    if (tid == 0) {
        float v0 = -1e30f; int i0 = 0;
        for (int e = 0; e < EE; e++) if (lg[e] > v0) { v0 = lg[e]; i0 = e; }
        float v1 = -1e30f; int i1 = 0;
        for (int e = 0; e < EE; e++) if (e != i0 && lg[e] > v1) { v1 = lg[e]; i1 = e; }
        float e1 = __expf(v1 - v0);
        float w0 = 1.f / (1.f + e1);
        float w1 = e1 / (1.f + e1);
        int p0 = atomicAdd(&g_cnt[i0], 1);
        g_tok[i0*NT + p0] = t; g_slotid[i0*NT + p0] = 2*t;     g_wt[i0*NT + p0] = w0;
        int p1 = atomicAdd(&g_cnt[i1], 1);
        g_tok[i1*NT + p1] = t; g_slotid[i1*NT + p1] = 2*t + 1; g_wt[i1*NT + p1] = w1;
    }
}

// ---------------- final combine ----------------
__global__ void combine_kernel(float* __restrict__ out) {
    int t = blockIdx.x;
    int c = threadIdx.x * 4;
    size_t idx = (size_t)t * DD + c;
    float4 a  = *(const float4*)&g_x1[idx];
    float4 c0 = *(const float4*)&g_contrib[(size_t)(2*t)*DD + c];
    float4 c1 = *(const float4*)&g_contrib[(size_t)(2*t+1)*DD + c];
    float4 o = make_float4(a.x+c0.x+c1.x, a.y+c0.y+c1.y, a.z+c0.z+c1.z, a.w+c0.w+c1.w);
    *(float4*)&out[idx] = o;
}

// ---------------- launch ----------------
extern "C" void kernel_launch(void* const* d_in, const int* in_sizes, int n_in,
                              void* d_out, int out_size) {
    const float* x    = (const float*)d_in[0];
    const float* ln_g = (const float*)d_in[1];
    const float* ln_b = (const float*)d_in[2];
    const float* Wq   = (const float*)d_in[3];
    const float* Wk   = (const float*)d_in[4];
    const float* Wv   = (const float*)d_in[5];
    const float* Wo   = (const float*)d_in[6];
    const float* Wg   = (const float*)d_in[7];
    const float* W1   = (const float*)d_in[8];
    const float* b1   = (const float*)d_in[9];
    const float* W2   = (const float*)d_in[10];
    const float* b2   = (const float*)d_in[11];
    float* out = (float*)d_out;

    __half *p_WqT, *p_WkT, *p_WvT, *p_WoT, *p_W1T, *p_W2T;
    cudaGetSymbolAddress((void**)&p_WqT, g_WqT16);
    cudaGetSymbolAddress((void**)&p_WkT, g_WkT16);
    cudaGetSymbolAddress((void**)&p_WvT, g_WvT16);
    cudaGetSymbolAddress((void**)&p_WoT, g_WoT16);
    cudaGetSymbolAddress((void**)&p_W1T, g_W1T16);
    cudaGetSymbolAddress((void**)&p_W2T, g_W2T16);

    cudaFuncSetAttribute(tc16_qkv,   cudaFuncAttributeMaxDynamicSharedMemorySize, GEMM16_SMEM);
    cudaFuncSetAttribute(tc16_oproj, cudaFuncAttributeMaxDynamicSharedMemorySize, GEMM16_SMEM);
    cudaFuncSetAttribute(tc16_ffn1,  cudaFuncAttributeMaxDynamicSharedMemorySize, GEMM16_SMEM);
    cudaFuncSetAttribute(tc16_ffn2,  cudaFuncAttributeMaxDynamicSharedMemorySize, GEMM16_SMEM);
    cudaFuncSetAttribute(attn16,     cudaFuncAttributeMaxDynamicSharedMemorySize, ATT_SMEM);

    // 0) weight transpose + fp16 convert
    dim3 trt(32, 8);
    tr16_kernel<<<dim3(32, 32, 1), trt>>>(Wq, p_WqT, DD, DD);
    tr16_kernel<<<dim3(32, 32, 1), trt>>>(Wk, p_WkT, DD, DD);
    tr16_kernel<<<dim3(32, 32, 1), trt>>>(Wv, p_WvT, DD, DD);
    tr16_kernel<<<dim3(32, 32, 1), trt>>>(Wo, p_WoT, DD, DD);
    tr16_kernel<<<dim3(FF/32, DD/32, EE), trt>>>(W1, p_W1T, DD, FF);
    tr16_kernel<<<dim3(DD/32, FF/32, EE), trt>>>(W2, p_W2T, FF, DD);
    // 1) layernorm (fp16 out)
    ln_kernel<<<NT, 256>>>(x, ln_g, ln_b);
    // 2) QKV projections (fp16 mma; V written transposed)
    tc16_qkv<<<dim3(DD/128, NT/128, 3), 256, GEMM16_SMEM>>>(p_WqT, p_WkT, p_WvT);
    // 3) fp16 flash attention (ldmatrix)
    attn16<<<dim3(SS/128, BB*HH), 256, ATT_SMEM>>>();
    // 4) O projection + residual
    tc16_oproj<<<dim3(DD/128, NT/128), 256, GEMM16_SMEM>>>(p_WoT, x);
    // 5) gate + binning
    zero_cnt_kernel<<<1, 32>>>();
    gate_kernel<<<NT, 256>>>(Wg);
    // 6) grouped expert FFN (fp16 mma)
    tc16_ffn1<<<dim3(FF/128, NT/128, EE), 256, GEMM16_SMEM>>>(p_W1T, b1);
    tc16_ffn2<<<dim3(DD/128, NT/128, EE), 256, GEMM16_SMEM>>>(p_W2T, b2);
    // 7) combine + residual 2
    combine_kernel<<<NT, 256>>>(out);
}

// round 14
// speedup vs baseline: 1.4830x; 1.4830x over previous
#include <cuda_runtime.h>
#include <cuda_fp16.h>
#include <cstdint>
#include <math.h>

// Problem dims
#define BB 2
#define SS 2048
#define DD 1024
#define HH 16
#define DH 64
#define FF 4096
#define EE 8
#define NT (BB*SS)   // 4096 tokens

// ---------------- scratch ----------------
__device__ __half g_h16[NT*DD];
__device__ __half g_q16[NT*DD];
__device__ __half g_k16[NT*DD];
__device__ __half g_vT16[(size_t)BB*HH*DH*SS];  // V transposed: [bh][d][s]
__device__ __half g_attn16[NT*DD];
__device__ float  g_x1[NT*DD];
__device__ __half g_x116[NT*DD];
__device__ int    g_cnt[EE];
__device__ int    g_tok[EE*NT];
__device__ int    g_slotid[EE*NT];
__device__ float  g_wt[EE*NT];
__device__ __half g_h116[(size_t)EE*NT*FF];
__device__ float  g_contrib[(size_t)2*NT*DD];
__device__ __half g_WqT16[DD*DD];
__device__ __half g_WkT16[DD*DD];
__device__ __half g_WvT16[DD*DD];
__device__ __half g_WoT16[DD*DD];
__device__ __half g_W1T16[(size_t)EE*(size_t)FF*DD];
__device__ __half g_W2T16[(size_t)EE*(size_t)DD*FF];

// ---------------- cp.async helpers ----------------
__device__ __forceinline__ void cpa16(const void* dst, const void* src) {
    unsigned d = (unsigned)__cvta_generic_to_shared(dst);
    asm volatile("cp.async.cg.shared.global [%0], [%1], 16;" :: "r"(d), "l"(src));
}
#define CPA_COMMIT()  asm volatile("cp.async.commit_group;")
#define CPA_WAIT(N)   asm volatile("cp.async.wait_group %0;" :: "n"(N))

// fp16 m16n8k16, fp32 accum
__device__ __forceinline__ void mma16(float (&c)[4], const uint32_t (&a)[4],
                                      uint32_t b0, uint32_t b1) {
    asm volatile("mma.sync.aligned.m16n8k16.row.col.f32.f16.f16.f32 "
        "{%0,%1,%2,%3}, {%4,%5,%6,%7}, {%8,%9}, {%0,%1,%2,%3};"
        : "+f"(c[0]), "+f"(c[1]), "+f"(c[2]), "+f"(c[3])
        : "r"(a[0]), "r"(a[1]), "r"(a[2]), "r"(a[3]), "r"(b0), "r"(b1));
}
// ldmatrix x4 (b16)
__device__ __forceinline__ void ldsm4(uint32_t (&r)[4], uint32_t addr) {
    asm volatile("ldmatrix.sync.aligned.m8n8.x4.shared.b16 {%0,%1,%2,%3}, [%4];"
        : "=r"(r[0]), "=r"(r[1]), "=r"(r[2]), "=r"(r[3]) : "r"(addr));
}

// ---------------- fp16 GEMM core (ldmatrix fragments, single barrier per K-slab) ----------------
#define HSTR 40
#define STG_HALVES (128*HSTR)
#define GEMM16_SMEM (8*STG_HALVES*2)

__device__ __forceinline__ void gemm16_core(const __half* a_src, const __half* b_src,
                                            int Kd, float (&acc)[4][4][4], __half* smem) {
    const int t = threadIdx.x;
    const int lane = t & 31, warp = t >> 5;
    const int wm = (warp >> 2) * 64, wn = (warp & 3) * 32;
    const int r = t >> 1, h = t & 1;

    __half* Asm = smem;
    __half* Bsm = smem + 4 * STG_HALVES;
    __half* ad0 = Asm + (size_t)r * HSTR + h * 16;
    __half* bd0 = Bsm + (size_t)r * HSTR + h * 16;

    const int a_row = (lane & 7) + ((lane >> 3) & 1) * 8;
    const int a_col = (lane >> 4) * 8;
    const int b_row = (lane & 7) + (lane >> 4) * 8;
    const int b_col = ((lane >> 3) & 1) * 8;
    uint32_t As_u = (uint32_t)__cvta_generic_to_shared(Asm);
    uint32_t Bs_u = (uint32_t)__cvta_generic_to_shared(Bsm);
    uint32_t aoff[4];
#pragma unroll
    for (int i = 0; i < 4; i++)
        aoff[i] = ((wm + i*16 + a_row) * HSTR + a_col) * 2;
    uint32_t boff0 = ((wn +      b_row) * HSTR + b_col) * 2;
    uint32_t boff1 = ((wn + 16 + b_row) * HSTR + b_col) * 2;

#define LD_STAGE(s, buf) { \
        const __half* as_ = a_src + (s) * 32; \
        const __half* bs_ = b_src + (s) * 32; \
        __half* ad_ = ad0 + (buf) * STG_HALVES; \
        __half* bd_ = bd0 + (buf) * STG_HALVES; \
        cpa16(ad_, as_); cpa16(ad_ + 8, as_ + 8); \
        cpa16(bd_, bs_); cpa16(bd_ + 8, bs_ + 8); }

    const int steps = Kd / 32;
    LD_STAGE(0, 0); CPA_COMMIT();
    LD_STAGE(1, 1); CPA_COMMIT();
    LD_STAGE(2, 2); CPA_COMMIT();

    for (int s = 0; s < steps; s++) {
        CPA_WAIT(2);
        __syncthreads();
        const int nx = s + 3;
        if (nx < steps) LD_STAGE(nx, nx & 3);
        CPA_COMMIT();
        const uint32_t Asb = As_u + (s & 3) * STG_HALVES * 2;
        const uint32_t Bsb = Bs_u + (s & 3) * STG_HALVES * 2;
#pragma unroll
        for (int ks = 0; ks < 2; ks++) {
            const uint32_t kadd = ks * 32;
            uint32_t a[4][4], b0[4], b1[4];
#pragma unroll
            for (int i = 0; i < 4; i++) ldsm4(a[i], Asb + aoff[i] + kadd);
            ldsm4(b0, Bsb + boff0 + kadd);
            ldsm4(b1, Bsb + boff1 + kadd);
#pragma unroll
            for (int i = 0; i < 4; i++) {
                mma16(acc[i][0], a[i], b0[0], b0[1]);
                mma16(acc[i][1], a[i], b0[2], b0[3]);
                mma16(acc[i][2], a[i], b1[0], b1[1]);
                mma16(acc[i][3], a[i], b1[2], b1[3]);
            }
        }
    }
#undef LD_STAGE
}

// ---------------- transpose + fp32->fp16 ----------------
__global__ void tr16_kernel(const float* __restrict__ src, __half* __restrict__ dst,
                            int R, int C) {
    __shared__ float tl[32][33];
    const size_t zsrc = (size_t)blockIdx.z * R * C;
    const int bx = blockIdx.x * 32, by = blockIdx.y * 32;
    const int tx = threadIdx.x, ty = threadIdx.y;
#pragma unroll
    for (int i = 0; i < 32; i += 8)
        tl[ty + i][tx] = src[zsrc + (size_t)(by + ty + i) * C + bx + tx];
    __syncthreads();
#pragma unroll
    for (int i = 0; i < 32; i += 8)
        dst[zsrc + (size_t)(bx + ty + i) * R + by + tx] = __float2half(tl[tx][ty + i]);
}

// ---------------- layernorm (fp16 out) ----------------
__global__ void ln_kernel(const float* __restrict__ x, const float* __restrict__ g,
                          const float* __restrict__ b) {
    __shared__ float red[256];
    int t = blockIdx.x, tid = threadIdx.x;
    const float* xr = x + (size_t)t * DD;
    float v[4], s = 0.f, s2 = 0.f;
#pragma unroll
    for (int i = 0; i < 4; i++) {
        float vv = xr[tid + i*256];
        v[i] = vv; s += vv; s2 += vv*vv;
    }
    red[tid] = s; __syncthreads();
    for (int o = 128; o > 0; o >>= 1) { if (tid < o) red[tid] += red[tid+o]; __syncthreads(); }
    float mean = red[0] * (1.f/DD);
    __syncthreads();
    red[tid] = s2; __syncthreads();
    for (int o = 128; o > 0; o >>= 1) { if (tid < o) red[tid] += red[tid+o]; __syncthreads(); }
    float var = red[0] * (1.f/DD) - mean*mean;
    float rs = rsqrtf(var + 1e-5f);
    __half* out = g_h16 + (size_t)t * DD;
#pragma unroll
    for (int i = 0; i < 4; i++) {
        int c = tid + i*256;
        out[c] = __float2half((v[i]-mean)*rs*g[c] + b[c]);
    }
}

// ---------------- QKV (fp16 mma; Q/K fp16 token-major, V transposed) ----------------
__global__ void tc16_qkv(const __half* __restrict__ BqT, const __half* __restrict__ BkT,
                         const __half* __restrict__ BvT) {
    extern __shared__ __half smh[];
    const __half* BT = blockIdx.z == 0 ? BqT : blockIdx.z == 1 ? BkT : BvT;
    const int m0 = blockIdx.y * 128, n0 = blockIdx.x * 128;
    const int t = threadIdx.x, lane = t & 31, warp = t >> 5;
    const int g = lane >> 2, q = lane & 3;
    const int wm = (warp >> 2) * 64, wn = (warp & 3) * 32;
    const int r = t >> 1, h = t & 1;
    float acc[4][4][4] = {};
    const __half* a_src = g_h16 + (size_t)(m0 + r) * DD + h * 16;
    const __half* b_src = BT + (size_t)(n0 + r) * DD + h * 16;
    gemm16_core(a_src, b_src, DD, acc, smh);

    if (blockIdx.z == 2) {
#pragma unroll
        for (int i = 0; i < 4; i++) {
            int r0 = m0 + wm + i*16 + g;
#pragma unroll
            for (int j = 0; j < 4; j++) {
                int c0 = n0 + wn + j*8 + 2*q;
                int hh = c0 >> 6, dd = c0 & 63;
#pragma unroll
                for (int hf = 0; hf < 2; hf++) {
                    int row = r0 + hf*8;
                    int b_ = row >> 11, s_ = row & 2047;
                    size_t basev = ((size_t)(b_*HH + hh) * DH);
                    g_vT16[(basev + dd)     * SS + s_] = __float2half(acc[i][j][hf*2+0]);
                    g_vT16[(basev + dd + 1) * SS + s_] = __float2half(acc[i][j][hf*2+1]);
                }
            }
        }
    } else {
        __half* C = blockIdx.z == 0 ? g_q16 : g_k16;
#pragma unroll
        for (int i = 0; i < 4; i++) {
            int r0 = m0 + wm + i*16 + g;
#pragma unroll
            for (int j = 0; j < 4; j++) {
                int c0 = n0 + wn + j*8 + 2*q;
                *(__half2*)&C[(size_t)r0 * DD + c0] =
                    __floats2half2_rn(acc[i][j][0], acc[i][j][1]);
                *(__half2*)&C[(size_t)(r0+8) * DD + c0] =
                    __floats2half2_rn(acc[i][j][2], acc[i][j][3]);
            }
        }
    }
}

// ---------------- fp16 flash attention (ldmatrix fragments) ----------------
#define AST 72
#define ATT_SMEM ((128*AST + 2*64*AST + 2*64*AST) * 2)
__global__ void attn16() {
    extern __shared__ __half ash[];
    __half (*Qs)[AST]       = (__half(*)[AST])ash;                       // [128][72], reused as P
    __half (*Ks)[64][AST]   = (__half(*)[64][AST])(ash + 128*AST);
    __half (*Vts)[64][AST]  = (__half(*)[64][AST])(ash + 128*AST + 2*64*AST);

    const int tid = threadIdx.x;
    const int lane = tid & 31, w = tid >> 5;
    const int g = lane >> 2, q = lane & 3;
    const int bh = blockIdx.y, b = bh >> 4, h = bh & 15;
    const int q0 = blockIdx.x * 128;
    const size_t tokbase = ((size_t)b*SS)*DD + h*DH;
    const size_t vtbase  = (size_t)bh * DH * SS;
    const int pr = w * 16;

    // ldmatrix per-thread addressing
    const int a_row = (lane & 7) + ((lane >> 3) & 1) * 8;
    const int a_col = (lane >> 4) * 8;
    const int b_row = (lane & 7) + (lane >> 4) * 8;
    const int b_col = ((lane >> 3) & 1) * 8;
    const uint32_t Qs_u  = (uint32_t)__cvta_generic_to_shared(Qs);
    const uint32_t Ks_u  = (uint32_t)__cvta_generic_to_shared(Ks);
    const uint32_t Vts_u = (uint32_t)__cvta_generic_to_shared(Vts);
    const uint32_t a_off = ((pr + a_row) * AST + a_col) * 2;   // within Qs/Ps
    const uint32_t KBUF = 64 * AST * 2;                        // bytes per K/V buffer

    { // Q tile (group A, with KV tile 0)
        int r = tid >> 1, cq = (tid & 1) * 32;
        const __half* src = g_q16 + tokbase + (size_t)(q0 + r)*DD + cq;
        cpa16(&Qs[r][cq],      src);      cpa16(&Qs[r][cq + 8],  src + 8);
        cpa16(&Qs[r][cq + 16], src + 16); cpa16(&Qs[r][cq + 24], src + 24);
    }
    {
        int r = tid >> 2, cq = (tid & 3) * 16;
        const __half* ksrc = g_k16 + tokbase + (size_t)r*DD + cq;
        cpa16(&Ks[0][r][cq], ksrc); cpa16(&Ks[0][r][cq + 8], ksrc + 8);
        const __half* vsrc = g_vT16 + vtbase + (size_t)r*SS + cq;
        cpa16(&Vts[0][r][cq], vsrc); cpa16(&Vts[0][r][cq + 8], vsrc + 8);
    }
    CPA_COMMIT();
    {
        int r = tid >> 2, cq = (tid & 3) * 16;
        const __half* ksrc = g_k16 + tokbase + (size_t)(64 + r)*DD + cq;
        cpa16(&Ks[1][r][cq], ksrc); cpa16(&Ks[1][r][cq + 8], ksrc + 8);
        const __half* vsrc = g_vT16 + vtbase + (size_t)r*SS + 64 + cq;
        cpa16(&Vts[1][r][cq], vsrc); cpa16(&Vts[1][r][cq + 8], vsrc + 8);
    }
    CPA_COMMIT();

    CPA_WAIT(1);
    __syncthreads();

    uint32_t aq[4][4];
#pragma unroll
    for (int ks = 0; ks < 4; ks++) ldsm4(aq[ks], Qs_u + a_off + ks*32);

    float m0r = -1e30f, m1r = -1e30f, l0 = 0.f, l1 = 0.f;
    float acc_o[8][4];
#pragma unroll
    for (int j = 0; j < 8; j++) { acc_o[j][0]=0.f; acc_o[j][1]=0.f; acc_o[j][2]=0.f; acc_o[j][3]=0.f; }
    __half (*Ps)[AST] = Qs;

    for (int kt = 0; kt < SS/64; kt++) {
        CPA_WAIT(1);
        __syncthreads();
        const uint32_t kb_u = Ks_u  + (kt & 1) * KBUF;
        const uint32_t vb_u = Vts_u + (kt & 1) * KBUF;

        // scores (fp16 k16) — B fragments via ldmatrix
        float s[8][4];
#pragma unroll
        for (int j = 0; j < 8; j++) { s[j][0]=0.f; s[j][1]=0.f; s[j][2]=0.f; s[j][3]=0.f; }
#pragma unroll
        for (int ks = 0; ks < 4; ks++) {
            const uint32_t kadd = ks * 32;
#pragma unroll
            for (int p = 0; p < 4; p++) {
                uint32_t bk[4];
                ldsm4(bk, kb_u + ((p*16 + b_row) * AST + b_col) * 2 + kadd);
                mma16(s[2*p],   aq[ks], bk[0], bk[1]);
                mma16(s[2*p+1], aq[ks], bk[2], bk[3]);
            }
        }
        // online softmax (scale 0.125)
        float mx0 = m0r, mx1 = m1r;
#pragma unroll
        for (int j = 0; j < 8; j++) {
            s[j][0] *= 0.125f; s[j][1] *= 0.125f; s[j][2] *= 0.125f; s[j][3] *= 0.125f;
            mx0 = fmaxf(mx0, fmaxf(s[j][0], s[j][1]));
            mx1 = fmaxf(mx1, fmaxf(s[j][2], s[j][3]));
        }
        mx0 = fmaxf(mx0, __shfl_xor_sync(0xffffffffu, mx0, 1));
        mx0 = fmaxf(mx0, __shfl_xor_sync(0xffffffffu, mx0, 2));
        mx1 = fmaxf(mx1, __shfl_xor_sync(0xffffffffu, mx1, 1));
        mx1 = fmaxf(mx1, __shfl_xor_sync(0xffffffffu, mx1, 2));
        float alpha0 = __expf(m0r - mx0), alpha1 = __expf(m1r - mx1);
        m0r = mx0; m1r = mx1;
        float ps0 = 0.f, ps1 = 0.f;
#pragma unroll
        for (int j = 0; j < 8; j++) {
            s[j][0] = __expf(s[j][0] - mx0); ps0 += s[j][0];
            s[j][1] = __expf(s[j][1] - mx0); ps0 += s[j][1];
            s[j][2] = __expf(s[j][2] - mx1); ps1 += s[j][2];
            s[j][3] = __expf(s[j][3] - mx1); ps1 += s[j][3];
        }
        ps0 += __shfl_xor_sync(0xffffffffu, ps0, 1);
        ps0 += __shfl_xor_sync(0xffffffffu, ps0, 2);
        ps1 += __shfl_xor_sync(0xffffffffu, ps1, 1);
        ps1 += __shfl_xor_sync(0xffffffffu, ps1, 2);
        l0 = l0 * alpha0 + ps0;
        l1 = l1 * alpha1 + ps1;
#pragma unroll
        for (int j = 0; j < 8; j++) {
            acc_o[j][0] *= alpha0; acc_o[j][1] *= alpha0;
            acc_o[j][2] *= alpha1; acc_o[j][3] *= alpha1;
        }
        // stash P (fp16) into warp-local rows
#pragma unroll
        for (int j = 0; j < 8; j++) {
            *(__half2*)&Ps[pr+g][j*8 + 2*q]   = __floats2half2_rn(s[j][0], s[j][1]);
            *(__half2*)&Ps[pr+8+g][j*8 + 2*q] = __floats2half2_rn(s[j][2], s[j][3]);
        }
        __syncwarp();
        // PV (fp16 k16) — A and B fragments via ldmatrix
#pragma unroll
        for (int ks = 0; ks < 4; ks++) {
            const uint32_t kadd = ks * 32;
            uint32_t ap[4];
            ldsm4(ap, Qs_u + a_off + kadd);   // Ps overlays Qs
#pragma unroll
            for (int p = 0; p < 4; p++) {
                uint32_t bv[4];
                ldsm4(bv, vb_u + ((p*16 + b_row) * AST + b_col) * 2 + kadd);
                mma16(acc_o[2*p],   ap, bv[0], bv[1]);
                mma16(acc_o[2*p+1], ap, bv[2], bv[3]);
            }
        }
        __syncthreads();
        if (kt + 2 < SS/64) {
            int r = tid >> 2, cq = (tid & 3) * 16;
            const int buf = kt & 1;
            const __half* ksrc = g_k16 + tokbase + (size_t)((kt+2)*64 + r)*DD + cq;
            cpa16(&Ks[buf][r][cq], ksrc); cpa16(&Ks[buf][r][cq + 8], ksrc + 8);
            const __half* vsrc = g_vT16 + vtbase + (size_t)r*SS + (kt+2)*64 + cq;
            cpa16(&Vts[buf][r][cq], vsrc); cpa16(&Vts[buf][r][cq + 8], vsrc + 8);
        }
        CPA_COMMIT();
    }
    // epilogue
    float inv0 = 1.f / l0, inv1 = 1.f / l1;
    int row0 = q0 + pr + g;
#pragma unroll
    for (int j = 0; j < 8; j++) {
        int col = j*8 + 2*q;
        *(__half2*)&g_attn16[tokbase + (size_t)row0 * DD + col] =
            __floats2half2_rn(acc_o[j][0]*inv0, acc_o[j][1]*inv0);
        *(__half2*)&g_attn16[tokbase + (size_t)(row0+8) * DD + col] =
            __floats2half2_rn(acc_o[j][2]*inv1, acc_o[j][3]*inv1);
    }
}

// ---------------- O-proj + residual ----------------
__global__ void tc16_oproj(const __half* __restrict__ BT, const float* __restrict__ Rres) {
    extern __shared__ __half smh[];
    const int m0 = blockIdx.y * 128, n0 = blockIdx.x * 128;
    const int t = threadIdx.x, lane = t & 31, warp = t >> 5;
    const int g = lane >> 2, q = lane & 3;
    const int wm = (warp >> 2) * 64, wn = (warp & 3) * 32;
    const int r = t >> 1, h = t & 1;
    float acc[4][4][4] = {};
    const __half* a_src = g_attn16 + (size_t)(m0 + r) * DD + h * 16;
    const __half* b_src = BT + (size_t)(n0 + r) * DD + h * 16;
    gemm16_core(a_src, b_src, DD, acc, smh);
#pragma unroll
    for (int i = 0; i < 4; i++) {
        int r0 = m0 + wm + i*16 + g;
#pragma unroll
        for (int j = 0; j < 4; j++) {
            int c0 = n0 + wn + j*8 + 2*q;
#pragma unroll
            for (int hf = 0; hf < 2; hf++) {
                size_t idx = (size_t)(r0 + hf*8) * DD + c0;
                float2 u = *(const float2*)&Rres[idx];
                float v0 = acc[i][j][hf*2+0] + u.x;
                float v1 = acc[i][j][hf*2+1] + u.y;
                *(float2*)&g_x1[idx] = make_float2(v0, v1);
                *(__half2*)&g_x116[idx] = __floats2half2_rn(v0, v1);
            }
        }
    }
}

// ---------------- FFN1 ----------------
__global__ void tc16_ffn1(const __half* __restrict__ W1T, const float* __restrict__ b1) {
    const int e = blockIdx.z;
    const int cnt = g_cnt[e];
    const int m0 = blockIdx.y * 128;
    if (m0 >= cnt) return;
    extern __shared__ __half smh[];
    const int n0 = blockIdx.x * 128;
    const int t = threadIdx.x, lane = t & 31, warp = t >> 5;
    const int g = lane >> 2, q = lane & 3;
    const int wm = (warp >> 2) * 64, wn = (warp & 3) * 32;
    const int r = t >> 1, h = t & 1;
    int ar = m0 + r; if (ar > cnt - 1) ar = cnt - 1;
    const int tok = g_tok[e * NT + ar];
    float acc[4][4][4] = {};
    const __half* a_src = g_x116 + (size_t)tok * DD + h * 16;
    const __half* b_src = W1T + (size_t)e * FF * DD + (size_t)(n0 + r) * DD + h * 16;
    gemm16_core(a_src, b_src, DD, acc, smh);
#pragma unroll
    for (int i = 0; i < 4; i++) {
        int r0 = m0 + wm + i*16 + g;
#pragma unroll
        for (int j = 0; j < 4; j++) {
            int c0 = n0 + wn + j*8 + 2*q;
            float bb0 = b1[e*FF + c0], bb1 = b1[e*FF + c0 + 1];
#pragma unroll
            for (int hf = 0; hf < 2; hf++) {
                int rr = r0 + hf*8;
                if (rr >= cnt) continue;
                float u0 = acc[i][j][hf*2+0] + bb0;
                float u1 = acc[i][j][hf*2+1] + bb1;
                float g0 = 0.5f*u0*(1.f + tanhf(0.7978845608028654f*(u0 + 0.044715f*u0*u0*u0)));
                float g1 = 0.5f*u1*(1.f + tanhf(0.7978845608028654f*(u1 + 0.044715f*u1*u1*u1)));
                *(__half2*)&g_h116[((size_t)e*NT + rr)*FF + c0] = __floats2half2_rn(g0, g1);
            }
        }
    }
}

// ---------------- FFN2 ----------------
__global__ void tc16_ffn2(const __half* __restrict__ W2T, const float* __restrict__ b2) {
    const int e = blockIdx.z;
    const int cnt = g_cnt[e];
    const int m0 = blockIdx.y * 128;
    if (m0 >= cnt) return;
    extern __shared__ __half smh[];
    const int n0 = blockIdx.x * 128;
    const int t = threadIdx.x, lane = t & 31, warp = t >> 5;
    const int g = lane >> 2, q = lane & 3;
    const int wm = (warp >> 2) * 64, wn = (warp & 3) * 32;
    const int r = t >> 1, h = t & 1;
    int ar = m0 + r; if (ar > cnt - 1) ar = cnt - 1;
    float acc[4][4][4] = {};
    const __half* a_src = g_h116 + ((size_t)e*NT + ar) * FF + h * 16;
    const __half* b_src = W2T + (size_t)e * DD * FF + (size_t)(n0 + r) * FF + h * 16;
    gemm16_core(a_src, b_src, FF, acc, smh);
#pragma unroll
    for (int i = 0; i < 4; i++) {
        int r0 = m0 + wm + i*16 + g;
#pragma unroll
        for (int j = 0; j < 4; j++) {
            int c0 = n0 + wn + j*8 + 2*q;
            float bb0 = b2[e*DD + c0], bb1 = b2[e*DD + c0 + 1];
#pragma unroll
            for (int hf = 0; hf < 2; hf++) {
                int rr = r0 + hf*8;
                if (rr >= cnt) continue;
                int slot = g_slotid[e*NT + rr];
                float w  = g_wt[e*NT + rr];
                *(float2*)&g_contrib[(size_t)slot * DD + c0] =
                    make_float2(w * (acc[i][j][hf*2+0] + bb0),
                                w * (acc[i][j][hf*2+1] + bb1));
            }
        }
    }
}

// ---------------- gate ----------------
__global__ void zero_cnt_kernel() { if (threadIdx.x < EE) g_cnt[threadIdx.x] = 0; }

__global__ void gate_kernel(const float* __restrict__ Wg) {
    __shared__ float lg[EE];
    int t = blockIdx.x, tid = threadIdx.x;
    int w = tid >> 5, lane = tid & 31;
    const float* xr = g_x1 + (size_t)t * DD;
    float s = 0.f;
    for (int d = lane; d < DD; d += 32) s += xr[d] * Wg[d*EE + w];
#pragma unroll
    for (int o = 16; o > 0; o >>= 1) s += __shfl_down_sync(0xffffffffu, s, o);
    if (lane == 0) lg[w] = s;
    __syncthreads();
    if (tid == 0) {
        float v0 = -1e30f; int i0 = 0;
        for (int e = 0; e < EE; e++) if (lg[e] > v0) { v0 = lg[e]; i0 = e; }
        float v1 = -1e30f; int i1 = 0;
        for (int e = 0; e < EE; e++) if (e != i0 && lg[e] > v1) { v1 = lg[e]; i1 = e; }
        float e1 = __expf(v1 - v0);
        float w0 = 1.f / (1.f + e1);
        float w1 = e1 / (1.f + e1);
        int p0 = atomicAdd(&g_cnt[i0], 1);
        g_tok[i0*NT + p0] = t; g_slotid[i0*NT + p0] = 2*t;     g_wt[i0*NT + p0] = w0;
        int p1 = atomicAdd(&g_cnt[i1], 1);
        g_tok[i1*NT + p1] = t; g_slotid[i1*NT + p1] = 2*t + 1; g_wt[i1*NT + p1] = w1;
    }
}

// ---------------- final combine ----------------
__global__ void combine_kernel(float* __restrict__ out) {
    int t = blockIdx.x;
    int c = threadIdx.x * 4;
    size_t idx = (size_t)t * DD + c;
    float4 a  = *(const float4*)&g_x1[idx];
    float4 c0 = *(const float4*)&g_contrib[(size_t)(2*t)*DD + c];
    float4 c1 = *(const float4*)&g_contrib[(size_t)(2*t+1)*DD + c];
    float4 o = make_float4(a.x+c0.x+c1.x, a.y+c0.y+c1.y, a.z+c0.z+c1.z, a.w+c0.w+c1.w);
    *(float4*)&out[idx] = o;
}

// ---------------- launch ----------------
extern "C" void kernel_launch(void* const* d_in, const int* in_sizes, int n_in,
                              void* d_out, int out_size) {
    const float* x    = (const float*)d_in[0];
    const float* ln_g = (const float*)d_in[1];
    const float* ln_b = (const float*)d_in[2];
    const float* Wq   = (const float*)d_in[3];
    const float* Wk   = (const float*)d_in[4];
    const float* Wv   = (const float*)d_in[5];
    const float* Wo   = (const float*)d_in[6];
    const float* Wg   = (const float*)d_in[7];
    const float* W1   = (const float*)d_in[8];
    const float* b1   = (const float*)d_in[9];
    const float* W2   = (const float*)d_in[10];
    const float* b2   = (const float*)d_in[11];
    float* out = (float*)d_out;

    __half *p_WqT, *p_WkT, *p_WvT, *p_WoT, *p_W1T, *p_W2T;
    cudaGetSymbolAddress((void**)&p_WqT, g_WqT16);
    cudaGetSymbolAddress((void**)&p_WkT, g_WkT16);
    cudaGetSymbolAddress((void**)&p_WvT, g_WvT16);
    cudaGetSymbolAddress((void**)&p_WoT, g_WoT16);
    cudaGetSymbolAddress((void**)&p_W1T, g_W1T16);
    cudaGetSymbolAddress((void**)&p_W2T, g_W2T16);

    cudaFuncSetAttribute(tc16_qkv,   cudaFuncAttributeMaxDynamicSharedMemorySize, GEMM16_SMEM);
    cudaFuncSetAttribute(tc16_oproj, cudaFuncAttributeMaxDynamicSharedMemorySize, GEMM16_SMEM);
    cudaFuncSetAttribute(tc16_ffn1,  cudaFuncAttributeMaxDynamicSharedMemorySize, GEMM16_SMEM);
    cudaFuncSetAttribute(tc16_ffn2,  cudaFuncAttributeMaxDynamicSharedMemorySize, GEMM16_SMEM);
    cudaFuncSetAttribute(attn16,     cudaFuncAttributeMaxDynamicSharedMemorySize, ATT_SMEM);

    // 0) weight transpose + fp16 convert
    dim3 trt(32, 8);
    tr16_kernel<<<dim3(32, 32, 1), trt>>>(Wq, p_WqT, DD, DD);
    tr16_kernel<<<dim3(32, 32, 1), trt>>>(Wk, p_WkT, DD, DD);
    tr16_kernel<<<dim3(32, 32, 1), trt>>>(Wv, p_WvT, DD, DD);
    tr16_kernel<<<dim3(32, 32, 1), trt>>>(Wo, p_WoT, DD, DD);
    tr16_kernel<<<dim3(FF/32, DD/32, EE), trt>>>(W1, p_W1T, DD, FF);
    tr16_kernel<<<dim3(DD/32, FF/32, EE), trt>>>(W2, p_W2T, FF, DD);
    // 1) layernorm (fp16 out)
    ln_kernel<<<NT, 256>>>(x, ln_g, ln_b);
    // 2) QKV projections (fp16 mma; V written transposed)
    tc16_qkv<<<dim3(DD/128, NT/128, 3), 256, GEMM16_SMEM>>>(p_WqT, p_WkT, p_WvT);
    // 3) fp16 flash attention (ldmatrix)
    attn16<<<dim3(SS/128, BB*HH), 256, ATT_SMEM>>>();
    // 4) O projection + residual
    tc16_oproj<<<dim3(DD/128, NT/128), 256, GEMM16_SMEM>>>(p_WoT, x);
    // 5) gate + binning
    zero_cnt_kernel<<<1, 32>>>();
    gate_kernel<<<NT, 256>>>(Wg);
    // 6) grouped expert FFN (fp16 mma)
    tc16_ffn1<<<dim3(FF/128, NT/128, EE), 256, GEMM16_SMEM>>>(p_W1T, b1);
    tc16_ffn2<<<dim3(DD/128, NT/128, EE), 256, GEMM16_SMEM>>>(p_W2T, b2);
    // 7) combine + residual 2
    combine_kernel<<<NT, 256>>>(out);
}

// round 15
// speedup vs baseline: 1.4888x; 1.0039x over previous
#include <cuda_runtime.h>
#include <cuda_fp16.h>
#include <cstdint>
#include <math.h>

// Problem dims
#define BB 2
#define SS 2048
#define DD 1024
#define HH 16
#define DH 64
#define FF 4096
#define EE 8
#define NT (BB*SS)   // 4096 tokens

// ---------------- scratch ----------------
__device__ __half g_h16[NT*DD];
__device__ __half g_q16[NT*DD];
__device__ __half g_k16[NT*DD];
__device__ __half g_vT16[(size_t)BB*HH*DH*SS];  // V transposed: [bh][d][s]
__device__ __half g_attn16[NT*DD];
__device__ float  g_x1[NT*DD];
__device__ __half g_x116[NT*DD];
__device__ int    g_cnt[EE];
__device__ int    g_tok[EE*NT];
__device__ int    g_slotid[EE*NT];
__device__ float  g_wt[EE*NT];
__device__ __half g_h116[(size_t)EE*NT*FF];
__device__ float  g_contrib[(size_t)2*NT*DD];
__device__ __half g_WqT16[DD*DD];
__device__ __half g_WkT16[DD*DD];
__device__ __half g_WvT16[DD*DD];
__device__ __half g_WoT16[DD*DD];
__device__ __half g_W1T16[(size_t)EE*(size_t)FF*DD];
__device__ __half g_W2T16[(size_t)EE*(size_t)DD*FF];

// ---------------- cp.async helpers ----------------
__device__ __forceinline__ void cpa16(const void* dst, const void* src) {
    unsigned d = (unsigned)__cvta_generic_to_shared(dst);
    asm volatile("cp.async.cg.shared.global [%0], [%1], 16;" :: "r"(d), "l"(src));
}
#define CPA_COMMIT()  asm volatile("cp.async.commit_group;")
#define CPA_WAIT(N)   asm volatile("cp.async.wait_group %0;" :: "n"(N))

// fp16 m16n8k16, fp32 accum
__device__ __forceinline__ void mma16(float (&c)[4], const uint32_t (&a)[4],
                                      uint32_t b0, uint32_t b1) {
    asm volatile("mma.sync.aligned.m16n8k16.row.col.f32.f16.f16.f32 "
        "{%0,%1,%2,%3}, {%4,%5,%6,%7}, {%8,%9}, {%0,%1,%2,%3};"
        : "+f"(c[0]), "+f"(c[1]), "+f"(c[2]), "+f"(c[3])
        : "r"(a[0]), "r"(a[1]), "r"(a[2]), "r"(a[3]), "r"(b0), "r"(b1));
}
// ldmatrix x4 (b16)
__device__ __forceinline__ void ldsm4(uint32_t (&r)[4], uint32_t addr) {
    asm volatile("ldmatrix.sync.aligned.m8n8.x4.shared.b16 {%0,%1,%2,%3}, [%4];"
        : "=r"(r[0]), "=r"(r[1]), "=r"(r[2]), "=r"(r[3]) : "r"(addr));
}

// ---------------- fp16 GEMM core (ldmatrix fragments, single barrier per K-slab) ----------------
#define HSTR 40
#define STG_HALVES (128*HSTR)
#define GEMM16_SMEM (8*STG_HALVES*2)

__device__ __forceinline__ void gemm16_core(const __half* a_src, const __half* b_src,
                                            int Kd, float (&acc)[4][4][4], __half* smem) {
    const int t = threadIdx.x;
    const int lane = t & 31, warp = t >> 5;
    const int wm = (warp >> 2) * 64, wn = (warp & 3) * 32;
    const int r = t >> 1, h = t & 1;

    __half* Asm = smem;
    __half* Bsm = smem + 4 * STG_HALVES;
    __half* ad0 = Asm + (size_t)r * HSTR + h * 16;
    __half* bd0 = Bsm + (size_t)r * HSTR + h * 16;

    const int a_row = (lane & 7) + ((lane >> 3) & 1) * 8;
    const int a_col = (lane >> 4) * 8;
    const int b_row = (lane & 7) + (lane >> 4) * 8;
    const int b_col = ((lane >> 3) & 1) * 8;
    uint32_t As_u = (uint32_t)__cvta_generic_to_shared(Asm);
    uint32_t Bs_u = (uint32_t)__cvta_generic_to_shared(Bsm);
    uint32_t aoff[4];
#pragma unroll
    for (int i = 0; i < 4; i++)
        aoff[i] = ((wm + i*16 + a_row) * HSTR + a_col) * 2;
    uint32_t boff0 = ((wn +      b_row) * HSTR + b_col) * 2;
    uint32_t boff1 = ((wn + 16 + b_row) * HSTR + b_col) * 2;

#define LD_STAGE(s, buf) { \
        const __half* as_ = a_src + (s) * 32; \
        const __half* bs_ = b_src + (s) * 32; \
        __half* ad_ = ad0 + (buf) * STG_HALVES; \
        __half* bd_ = bd0 + (buf) * STG_HALVES; \
        cpa16(ad_, as_); cpa16(ad_ + 8, as_ + 8); \
        cpa16(bd_, bs_); cpa16(bd_ + 8, bs_ + 8); }

    const int steps = Kd / 32;
    LD_STAGE(0, 0); CPA_COMMIT();
    LD_STAGE(1, 1); CPA_COMMIT();
    LD_STAGE(2, 2); CPA_COMMIT();

    for (int s = 0; s < steps; s++) {
        CPA_WAIT(2);
        __syncthreads();
        const int nx = s + 3;
        if (nx < steps) LD_STAGE(nx, nx & 3);
        CPA_COMMIT();
        const uint32_t Asb = As_u + (s & 3) * STG_HALVES * 2;
        const uint32_t Bsb = Bs_u + (s & 3) * STG_HALVES * 2;
#pragma unroll
        for (int ks = 0; ks < 2; ks++) {
            const uint32_t kadd = ks * 32;
            uint32_t a[4][4], b0[4], b1[4];
#pragma unroll
            for (int i = 0; i < 4; i++) ldsm4(a[i], Asb + aoff[i] + kadd);
            ldsm4(b0, Bsb + boff0 + kadd);
            ldsm4(b1, Bsb + boff1 + kadd);
#pragma unroll
            for (int i = 0; i < 4; i++) {
                mma16(acc[i][0], a[i], b0[0], b0[1]);
                mma16(acc[i][1], a[i], b0[2], b0[3]);
                mma16(acc[i][2], a[i], b1[0], b1[1]);
                mma16(acc[i][3], a[i], b1[2], b1[3]);
            }
        }
    }
#undef LD_STAGE
}

// ---------------- transpose + fp32->fp16 ----------------
__global__ void tr16_kernel(const float* __restrict__ src, __half* __restrict__ dst,
                            int R, int C) {
    __shared__ float tl[32][33];
    const size_t zsrc = (size_t)blockIdx.z * R * C;
    const int bx = blockIdx.x * 32, by = blockIdx.y * 32;
    const int tx = threadIdx.x, ty = threadIdx.y;
#pragma unroll
    for (int i = 0; i < 32; i += 8)
        tl[ty + i][tx] = src[zsrc + (size_t)(by + ty + i) * C + bx + tx];
    __syncthreads();
#pragma unroll
    for (int i = 0; i < 32; i += 8)
        dst[zsrc + (size_t)(bx + ty + i) * R + by + tx] = __float2half(tl[tx][ty + i]);
}

// ---------------- layernorm (fp16 out) ----------------
__global__ void ln_kernel(const float* __restrict__ x, const float* __restrict__ g,
                          const float* __restrict__ b) {
    __shared__ float red[256];
    int t = blockIdx.x, tid = threadIdx.x;
    const float* xr = x + (size_t)t * DD;
    float v[4], s = 0.f, s2 = 0.f;
#pragma unroll
    for (int i = 0; i < 4; i++) {
        float vv = xr[tid + i*256];
        v[i] = vv; s += vv; s2 += vv*vv;
    }
    red[tid] = s; __syncthreads();
    for (int o = 128; o > 0; o >>= 1) { if (tid < o) red[tid] += red[tid+o]; __syncthreads(); }
    float mean = red[0] * (1.f/DD);
    __syncthreads();
    red[tid] = s2; __syncthreads();
    for (int o = 128; o > 0; o >>= 1) { if (tid < o) red[tid] += red[tid+o]; __syncthreads(); }
    float var = red[0] * (1.f/DD) - mean*mean;
    float rs = rsqrtf(var + 1e-5f);
    __half* out = g_h16 + (size_t)t * DD;
#pragma unroll
    for (int i = 0; i < 4; i++) {
        int c = tid + i*256;
        out[c] = __float2half((v[i]-mean)*rs*g[c] + b[c]);
    }
}

// ---------------- QKV (fp16 mma; Q/K fp16 token-major, V transposed) ----------------
__global__ void tc16_qkv(const __half* __restrict__ BqT, const __half* __restrict__ BkT,
                         const __half* __restrict__ BvT) {
    extern __shared__ __half smh[];
    const __half* BT = blockIdx.z == 0 ? BqT : blockIdx.z == 1 ? BkT : BvT;
    const int m0 = blockIdx.y * 128, n0 = blockIdx.x * 128;
    const int t = threadIdx.x, lane = t & 31, warp = t >> 5;
    const int g = lane >> 2, q = lane & 3;
    const int wm = (warp >> 2) * 64, wn = (warp & 3) * 32;
    const int r = t >> 1, h = t & 1;
    float acc[4][4][4] = {};
    const __half* a_src = g_h16 + (size_t)(m0 + r) * DD + h * 16;
    const __half* b_src = BT + (size_t)(n0 + r) * DD + h * 16;
    gemm16_core(a_src, b_src, DD, acc, smh);

    if (blockIdx.z == 2) {
#pragma unroll
        for (int i = 0; i < 4; i++) {
            int r0 = m0 + wm + i*16 + g;
#pragma unroll
            for (int j = 0; j < 4; j++) {
                int c0 = n0 + wn + j*8 + 2*q;
                int hh = c0 >> 6, dd = c0 & 63;
#pragma unroll
                for (int hf = 0; hf < 2; hf++) {
                    int row = r0 + hf*8;
                    int b_ = row >> 11, s_ = row & 2047;
                    size_t basev = ((size_t)(b_*HH + hh) * DH);
                    g_vT16[(basev + dd)     * SS + s_] = __float2half(acc[i][j][hf*2+0]);
                    g_vT16[(basev + dd + 1) * SS + s_] = __float2half(acc[i][j][hf*2+1]);
                }
            }
        }
    } else {
        __half* C = blockIdx.z == 0 ? g_q16 : g_k16;
#pragma unroll
        for (int i = 0; i < 4; i++) {
            int r0 = m0 + wm + i*16 + g;
#pragma unroll
            for (int j = 0; j < 4; j++) {
                int c0 = n0 + wn + j*8 + 2*q;
                *(__half2*)&C[(size_t)r0 * DD + c0] =
                    __floats2half2_rn(acc[i][j][0], acc[i][j][1]);
                *(__half2*)&C[(size_t)(r0+8) * DD + c0] =
                    __floats2half2_rn(acc[i][j][2], acc[i][j][3]);
            }
        }
    }
}

// ---------------- fp16 flash attention (ldmatrix fragments) ----------------
#define AST 72
#define ATT_SMEM ((128*AST + 2*64*AST + 2*64*AST) * 2)
__global__ void attn16() {
    extern __shared__ __half ash[];
    __half (*Qs)[AST]       = (__half(*)[AST])ash;                       // [128][72], reused as P
    __half (*Ks)[64][AST]   = (__half(*)[64][AST])(ash + 128*AST);
    __half (*Vts)[64][AST]  = (__half(*)[64][AST])(ash + 128*AST + 2*64*AST);

    const int tid = threadIdx.x;
    const int lane = tid & 31, w = tid >> 5;
    const int g = lane >> 2, q = lane & 3;
    const int bh = blockIdx.y, b = bh >> 4, h = bh & 15;
    const int q0 = blockIdx.x * 128;
    const size_t tokbase = ((size_t)b*SS)*DD + h*DH;
    const size_t vtbase  = (size_t)bh * DH * SS;
    const int pr = w * 16;

    // ldmatrix per-thread addressing
    const int a_row = (lane & 7) + ((lane >> 3) & 1) * 8;
    const int a_col = (lane >> 4) * 8;
    const int b_row = (lane & 7) + (lane >> 4) * 8;
    const int b_col = ((lane >> 3) & 1) * 8;
    const uint32_t Qs_u  = (uint32_t)__cvta_generic_to_shared(Qs);
    const uint32_t Ks_u  = (uint32_t)__cvta_generic_to_shared(Ks);
    const uint32_t Vts_u = (uint32_t)__cvta_generic_to_shared(Vts);
    const uint32_t a_off = ((pr + a_row) * AST + a_col) * 2;   // within Qs/Ps
    const uint32_t KBUF = 64 * AST * 2;                        // bytes per K/V buffer

    { // Q tile (group A, with KV tile 0)
        int r = tid >> 1, cq = (tid & 1) * 32;
        const __half* src = g_q16 + tokbase + (size_t)(q0 + r)*DD + cq;
        cpa16(&Qs[r][cq],      src);      cpa16(&Qs[r][cq + 8],  src + 8);
        cpa16(&Qs[r][cq + 16], src + 16); cpa16(&Qs[r][cq + 24], src + 24);
    }
    {
        int r = tid >> 2, cq = (tid & 3) * 16;
        const __half* ksrc = g_k16 + tokbase + (size_t)r*DD + cq;
        cpa16(&Ks[0][r][cq], ksrc); cpa16(&Ks[0][r][cq + 8], ksrc + 8);
        const __half* vsrc = g_vT16 + vtbase + (size_t)r*SS + cq;
        cpa16(&Vts[0][r][cq], vsrc); cpa16(&Vts[0][r][cq + 8], vsrc + 8);
    }
    CPA_COMMIT();
    {
        int r = tid >> 2, cq = (tid & 3) * 16;
        const __half* ksrc = g_k16 + tokbase + (size_t)(64 + r)*DD + cq;
        cpa16(&Ks[1][r][cq], ksrc); cpa16(&Ks[1][r][cq + 8], ksrc + 8);
        const __half* vsrc = g_vT16 + vtbase + (size_t)r*SS + 64 + cq;
        cpa16(&Vts[1][r][cq], vsrc); cpa16(&Vts[1][r][cq + 8], vsrc + 8);
    }
    CPA_COMMIT();

    CPA_WAIT(1);
    __syncthreads();

    uint32_t aq[4][4];
#pragma unroll
    for (int ks = 0; ks < 4; ks++) ldsm4(aq[ks], Qs_u + a_off + ks*32);

    float m0r = -1e30f, m1r = -1e30f, l0 = 0.f, l1 = 0.f;
    float acc_o[8][4];
#pragma unroll
    for (int j = 0; j < 8; j++) { acc_o[j][0]=0.f; acc_o[j][1]=0.f; acc_o[j][2]=0.f; acc_o[j][3]=0.f; }
    __half (*Ps)[AST] = Qs;

    for (int kt = 0; kt < SS/64; kt++) {
        CPA_WAIT(1);
        __syncthreads();
        const uint32_t kb_u = Ks_u  + (kt & 1) * KBUF;
        const uint32_t vb_u = Vts_u + (kt & 1) * KBUF;

        // scores (fp16 k16) — B fragments via ldmatrix
        float s[8][4];
#pragma unroll
        for (int j = 0; j < 8; j++) { s[j][0]=0.f; s[j][1]=0.f; s[j][2]=0.f; s[j][3]=0.f; }
#pragma unroll
        for (int ks = 0; ks < 4; ks++) {
            const uint32_t kadd = ks * 32;
#pragma unroll
            for (int p = 0; p < 4; p++) {
                uint32_t bk[4];
                ldsm4(bk, kb_u + ((p*16 + b_row) * AST + b_col) * 2 + kadd);
                mma16(s[2*p],   aq[ks], bk[0], bk[1]);
                mma16(s[2*p+1], aq[ks], bk[2], bk[3]);
            }
        }
        // online softmax (scale 0.125)
        float mx0 = m0r, mx1 = m1r;
#pragma unroll
        for (int j = 0; j < 8; j++) {
            s[j][0] *= 0.125f; s[j][1] *= 0.125f; s[j][2] *= 0.125f; s[j][3] *= 0.125f;
            mx0 = fmaxf(mx0, fmaxf(s[j][0], s[j][1]));
            mx1 = fmaxf(mx1, fmaxf(s[j][2], s[j][3]));
        }
        mx0 = fmaxf(mx0, __shfl_xor_sync(0xffffffffu, mx0, 1));
        mx0 = fmaxf(mx0, __shfl_xor_sync(0xffffffffu, mx0, 2));
        mx1 = fmaxf(mx1, __shfl_xor_sync(0xffffffffu, mx1, 1));
        mx1 = fmaxf(mx1, __shfl_xor_sync(0xffffffffu, mx1, 2));
        float alpha0 = __expf(m0r - mx0), alpha1 = __expf(m1r - mx1);
        m0r = mx0; m1r = mx1;
        float ps0 = 0.f, ps1 = 0.f;
#pragma unroll
        for (int j = 0; j < 8; j++) {
            s[j][0] = __expf(s[j][0] - mx0); ps0 += s[j][0];
            s[j][1] = __expf(s[j][1] - mx0); ps0 += s[j][1];
            s[j][2] = __expf(s[j][2] - mx1); ps1 += s[j][2];
            s[j][3] = __expf(s[j][3] - mx1); ps1 += s[j][3];
        }
        ps0 += __shfl_xor_sync(0xffffffffu, ps0, 1);
        ps0 += __shfl_xor_sync(0xffffffffu, ps0, 2);
        ps1 += __shfl_xor_sync(0xffffffffu, ps1, 1);
        ps1 += __shfl_xor_sync(0xffffffffu, ps1, 2);
        l0 = l0 * alpha0 + ps0;
        l1 = l1 * alpha1 + ps1;
#pragma unroll
        for (int j = 0; j < 8; j++) {
            acc_o[j][0] *= alpha0; acc_o[j][1] *= alpha0;
            acc_o[j][2] *= alpha1; acc_o[j][3] *= alpha1;
        }
        // stash P (fp16) into warp-local rows
#pragma unroll
        for (int j = 0; j < 8; j++) {
            *(__half2*)&Ps[pr+g][j*8 + 2*q]   = __floats2half2_rn(s[j][0], s[j][1]);
            *(__half2*)&Ps[pr+8+g][j*8 + 2*q] = __floats2half2_rn(s[j][2], s[j][3]);
        }
        __syncwarp();
        // PV (fp16 k16) — A and B fragments via ldmatrix
#pragma unroll
        for (int ks = 0; ks < 4; ks++) {
            const uint32_t kadd = ks * 32;
            uint32_t ap[4];
            ldsm4(ap, Qs_u + a_off + kadd);   // Ps overlays Qs
#pragma unroll
            for (int p = 0; p < 4; p++) {
                uint32_t bv[4];
                ldsm4(bv, vb_u + ((p*16 + b_row) * AST + b_col) * 2 + kadd);
                mma16(acc_o[2*p],   ap, bv[0], bv[1]);
                mma16(acc_o[2*p+1], ap, bv[2], bv[3]);
            }
        }
        __syncthreads();
        if (kt + 2 < SS/64) {
            int r = tid >> 2, cq = (tid & 3) * 16;
            const int buf = kt & 1;
            const __half* ksrc = g_k16 + tokbase + (size_t)((kt+2)*64 + r)*DD + cq;
            cpa16(&Ks[buf][r][cq], ksrc); cpa16(&Ks[buf][r][cq + 8], ksrc + 8);
            const __half* vsrc = g_vT16 + vtbase + (size_t)r*SS + (kt+2)*64 + cq;
            cpa16(&Vts[buf][r][cq], vsrc); cpa16(&Vts[buf][r][cq + 8], vsrc + 8);
        }
        CPA_COMMIT();
    }
    // epilogue
    float inv0 = 1.f / l0, inv1 = 1.f / l1;
    int row0 = q0 + pr + g;
#pragma unroll
    for (int j = 0; j < 8; j++) {
        int col = j*8 + 2*q;
        *(__half2*)&g_attn16[tokbase + (size_t)row0 * DD + col] =
            __floats2half2_rn(acc_o[j][0]*inv0, acc_o[j][1]*inv0);
        *(__half2*)&g_attn16[tokbase + (size_t)(row0+8) * DD + col] =
            __floats2half2_rn(acc_o[j][2]*inv1, acc_o[j][3]*inv1);
    }
}

// ---------------- O-proj + residual ----------------
__global__ void tc16_oproj(const __half* __restrict__ BT, const float* __restrict__ Rres) {
    extern __shared__ __half smh[];
    const int m0 = blockIdx.y * 128, n0 = blockIdx.x * 128;
    const int t = threadIdx.x, lane = t & 31, warp = t >> 5;
    const int g = lane >> 2, q = lane & 3;
    const int wm = (warp >> 2) * 64, wn = (warp & 3) * 32;
    const int r = t >> 1, h = t & 1;
    float acc[4][4][4] = {};
    const __half* a_src = g_attn16 + (size_t)(m0 + r) * DD + h * 16;
    const __half* b_src = BT + (size_t)(n0 + r) * DD + h * 16;
    gemm16_core(a_src, b_src, DD, acc, smh);
#pragma unroll
    for (int i = 0; i < 4; i++) {
        int r0 = m0 + wm + i*16 + g;
#pragma unroll
        for (int j = 0; j < 4; j++) {
            int c0 = n0 + wn + j*8 + 2*q;
#pragma unroll
            for (int hf = 0; hf < 2; hf++) {
                size_t idx = (size_t)(r0 + hf*8) * DD + c0;
                float2 u = *(const float2*)&Rres[idx];
                float v0 = acc[i][j][hf*2+0] + u.x;
                float v1 = acc[i][j][hf*2+1] + u.y;
                *(float2*)&g_x1[idx] = make_float2(v0, v1);
                *(__half2*)&g_x116[idx] = __floats2half2_rn(v0, v1);
            }
        }
    }
}

// ---------------- FFN1 ----------------
__global__ void tc16_ffn1(const __half* __restrict__ W1T, const float* __restrict__ b1) {
    const int e = blockIdx.z;
    const int cnt = g_cnt[e];
    const int m0 = blockIdx.y * 128;
    if (m0 >= cnt) return;
    extern __shared__ __half smh[];
    const int n0 = blockIdx.x * 128;
    const int t = threadIdx.x, lane = t & 31, warp = t >> 5;
    const int g = lane >> 2, q = lane & 3;
    const int wm = (warp >> 2) * 64, wn = (warp & 3) * 32;
    const int r = t >> 1, h = t & 1;
    int ar = m0 + r; if (ar > cnt - 1) ar = cnt - 1;
    const int tok = g_tok[e * NT + ar];
    float acc[4][4][4] = {};
    const __half* a_src = g_x116 + (size_t)tok * DD + h * 16;
    const __half* b_src = W1T + (size_t)e * FF * DD + (size_t)(n0 + r) * DD + h * 16;
    gemm16_core(a_src, b_src, DD, acc, smh);
#pragma unroll
    for (int i = 0; i < 4; i++) {
        int r0 = m0 + wm + i*16 + g;
#pragma unroll
        for (int j = 0; j < 4; j++) {
            int c0 = n0 + wn + j*8 + 2*q;
            float bb0 = b1[e*FF + c0], bb1 = b1[e*FF + c0 + 1];
#pragma unroll
            for (int hf = 0; hf < 2; hf++) {
                int rr = r0 + hf*8;
                if (rr >= cnt) continue;
                float u0 = acc[i][j][hf*2+0] + bb0;
                float u1 = acc[i][j][hf*2+1] + bb1;
                float g0 = 0.5f*u0*(1.f + tanhf(0.7978845608028654f*(u0 + 0.044715f*u0*u0*u0)));
                float g1 = 0.5f*u1*(1.f + tanhf(0.7978845608028654f*(u1 + 0.044715f*u1*u1*u1)));
                *(__half2*)&g_h116[((size_t)e*NT + rr)*FF + c0] = __floats2half2_rn(g0, g1);
            }
        }
    }
}

// ---------------- FFN2 ----------------
__global__ void tc16_ffn2(const __half* __restrict__ W2T, const float* __restrict__ b2) {
    const int e = blockIdx.z;
    const int cnt = g_cnt[e];
    const int m0 = blockIdx.y * 128;
    if (m0 >= cnt) return;
    extern __shared__ __half smh[];
    const int n0 = blockIdx.x * 128;
    const int t = threadIdx.x, lane = t & 31, warp = t >> 5;
    const int g = lane >> 2, q = lane & 3;
    const int wm = (warp >> 2) * 64, wn = (warp & 3) * 32;
    const int r = t >> 1, h = t & 1;
    int ar = m0 + r; if (ar > cnt - 1) ar = cnt - 1;
    float acc[4][4][4] = {};
    const __half* a_src = g_h116 + ((size_t)e*NT + ar) * FF + h * 16;
    const __half* b_src = W2T + (size_t)e * DD * FF + (size_t)(n0 + r) * FF + h * 16;
    gemm16_core(a_src, b_src, FF, acc, smh);
#pragma unroll
    for (int i = 0; i < 4; i++) {
        int r0 = m0 + wm + i*16 + g;
#pragma unroll
        for (int j = 0; j < 4; j++) {
            int c0 = n0 + wn + j*8 + 2*q;
            float bb0 = b2[e*DD + c0], bb1 = b2[e*DD + c0 + 1];
#pragma unroll
            for (int hf = 0; hf < 2; hf++) {
                int rr = r0 + hf*8;
                if (rr >= cnt) continue;
                int slot = g_slotid[e*NT + rr];
                float w  = g_wt[e*NT + rr];
                *(float2*)&g_contrib[(size_t)slot * DD + c0] =
                    make_float2(w * (acc[i][j][hf*2+0] + bb0),
                                w * (acc[i][j][hf*2+1] + bb1));
            }
        }
    }
}

// ---------------- gate ----------------
__global__ void zero_cnt_kernel() { if (threadIdx.x < EE) g_cnt[threadIdx.x] = 0; }

__global__ void gate_kernel(const float* __restrict__ Wg) {
    __shared__ float lg[EE];
    int t = blockIdx.x, tid = threadIdx.x;
    int w = tid >> 5, lane = tid & 31;
    const float* xr = g_x1 + (size_t)t * DD;
    float s = 0.f;
    for (int d = lane; d < DD; d += 32) s += xr[d] * Wg[d*EE + w];
#pragma unroll
    for (int o = 16; o > 0; o >>= 1) s += __shfl_down_sync(0xffffffffu, s, o);
    if (lane == 0) lg[w] = s;
    __syncthreads();
    if (tid == 0) {
        float v0 = -1e30f; int i0 = 0;
        for (int e = 0; e < EE; e++) if (lg[e] > v0) { v0 = lg[e]; i0 = e; }
        float v1 = -1e30f; int i1 = 0;
        for (int e = 0; e < EE; e++) if (e != i0 && lg[e] > v1) { v1 = lg[e]; i1 = e; }
        float e1 = __expf(v1 - v0);
        float w0 = 1.f / (1.f + e1);
        float w1 = e1 / (1.f + e1);
        int p0 = atomicAdd(&g_cnt[i0], 1);
        g_tok[i0*NT + p0] = t; g_slotid[i0*NT + p0] = 2*t;     g_wt[i0*NT + p0] = w0;
        int p1 = atomicAdd(&g_cnt[i1], 1);
        g_tok[i1*NT + p1] = t; g_slotid[i1*NT + p1] = 2*t + 1; g_wt[i1*NT + p1] = w1;
    }
}

// ---------------- final combine ----------------
__global__ void combine_kernel(float* __restrict__ out) {
    int t = blockIdx.x;
    int c = threadIdx.x * 4;
    size_t idx = (size_t)t * DD + c;
    float4 a  = *(const float4*)&g_x1[idx];
    float4 c0 = *(const float4*)&g_contrib[(size_t)(2*t)*DD + c];
    float4 c1 = *(const float4*)&g_contrib[(size_t)(2*t+1)*DD + c];
    float4 o = make_float4(a.x+c0.x+c1.x, a.y+c0.y+c1.y, a.z+c0.z+c1.z, a.w+c0.w+c1.w);
    *(float4*)&out[idx] = o;
}

// ---------------- launch ----------------
extern "C" void kernel_launch(void* const* d_in, const int* in_sizes, int n_in,
                              void* d_out, int out_size) {
    const float* x    = (const float*)d_in[0];
    const float* ln_g = (const float*)d_in[1];
    const float* ln_b = (const float*)d_in[2];
    const float* Wq   = (const float*)d_in[3];
    const float* Wk   = (const float*)d_in[4];
    const float* Wv   = (const float*)d_in[5];
    const float* Wo   = (const float*)d_in[6];
    const float* Wg   = (const float*)d_in[7];
    const float* W1   = (const float*)d_in[8];
    const float* b1   = (const float*)d_in[9];
    const float* W2   = (const float*)d_in[10];
    const float* b2   = (const float*)d_in[11];
    float* out = (float*)d_out;

    __half *p_WqT, *p_WkT, *p_WvT, *p_WoT, *p_W1T, *p_W2T;
    cudaGetSymbolAddress((void**)&p_WqT, g_WqT16);
    cudaGetSymbolAddress((void**)&p_WkT, g_WkT16);
    cudaGetSymbolAddress((void**)&p_WvT, g_WvT16);
    cudaGetSymbolAddress((void**)&p_WoT, g_WoT16);
    cudaGetSymbolAddress((void**)&p_W1T, g_W1T16);
    cudaGetSymbolAddress((void**)&p_W2T, g_W2T16);

    cudaFuncSetAttribute(tc16_qkv,   cudaFuncAttributeMaxDynamicSharedMemorySize, GEMM16_SMEM);
    cudaFuncSetAttribute(tc16_oproj, cudaFuncAttributeMaxDynamicSharedMemorySize, GEMM16_SMEM);
    cudaFuncSetAttribute(tc16_ffn1,  cudaFuncAttributeMaxDynamicSharedMemorySize, GEMM16_SMEM);
    cudaFuncSetAttribute(tc16_ffn2,  cudaFuncAttributeMaxDynamicSharedMemorySize, GEMM16_SMEM);
    cudaFuncSetAttribute(attn16,     cudaFuncAttributeMaxDynamicSharedMemorySize, ATT_SMEM);

    // 0) weight transpose + fp16 convert
    dim3 trt(32, 8);
    tr16_kernel<<<dim3(32, 32, 1), trt>>>(Wq, p_WqT, DD, DD);
    tr16_kernel<<<dim3(32, 32, 1), trt>>>(Wk, p_WkT, DD, DD);
    tr16_kernel<<<dim3(32, 32, 1), trt>>>(Wv, p_WvT, DD, DD);
    tr16_kernel<<<dim3(32, 32, 1), trt>>>(Wo, p_WoT, DD, DD);
    tr16_kernel<<<dim3(FF/32, DD/32, EE), trt>>>(W1, p_W1T, DD, FF);
    tr16_kernel<<<dim3(DD/32, FF/32, EE), trt>>>(W2, p_W2T, FF, DD);
    // 1) layernorm (fp16 out)
    ln_kernel<<<NT, 256>>>(x, ln_g, ln_b);
    // 2) QKV projections (fp16 mma; V written transposed)
    tc16_qkv<<<dim3(DD/128, NT/128, 3), 256, GEMM16_SMEM>>>(p_WqT, p_WkT, p_WvT);
    // 3) fp16 flash attention (ldmatrix)
    attn16<<<dim3(SS/128, BB*HH), 256, ATT_SMEM>>>();
    // 4) O projection + residual
    tc16_oproj<<<dim3(DD/128, NT/128), 256, GEMM16_SMEM>>>(p_WoT, x);
    // 5) gate + binning
    zero_cnt_kernel<<<1, 32>>>();
    gate_kernel<<<NT, 256>>>(Wg);
    // 6) grouped expert FFN (fp16 mma)
    tc16_ffn1<<<dim3(FF/128, NT/128, EE), 256, GEMM16_SMEM>>>(p_W1T, b1);
    tc16_ffn2<<<dim3(DD/128, NT/128, EE), 256, GEMM16_SMEM>>>(p_W2T, b2);
    // 7) combine + residual 2
    combine_kernel<<<NT, 256>>>(out);
}